// round 8
// baseline (speedup 1.0000x reference)
#include <cuda_runtime.h>
#include <cstdint>
#include <cstddef>

#define NSTEP 16384
#define S     512
#define CL    8            // CTAs per cluster
#define NCLUS_DIR 8        // clusters per direction
#define C     4            // chunks processed per cluster (sequential per step)
#define NCHUNK (NCLUS_DIR * C)          // 32 chunks per direction
#define LCHUNK (NSTEP / NCHUNK)         // 512
#define BURN  64
#define SLICE 64
#define NT    512
#define NW    16
#define NSTEPS_LOOP (LCHUNK - 1 + BURN) // 575

__device__ float g_alphas[(size_t)NSTEP * S];
__device__ float g_betas[(size_t)NSTEP * S];

static __device__ __forceinline__ uint32_t smem_u32(const void* p) {
    uint32_t a;
    asm("{ .reg .u64 t; cvta.to.shared.u64 t, %1; cvt.u32.u64 %0, t; }"
        : "=r"(a) : "l"(p));
    return a;
}
static __device__ __forceinline__ uint32_t my_rank() {
    uint32_t r; asm("mov.u32 %0, %%cluster_ctarank;" : "=r"(r)); return r;
}
static __device__ __forceinline__ uint32_t mapa_u32(uint32_t a, uint32_t rank) {
    uint32_t r;
    asm("mapa.shared::cluster.u32 %0, %1, %2;" : "=r"(r) : "r"(a), "r"(rank));
    return r;
}
static __device__ __forceinline__ void st_cluster(uint32_t a, float v) {
    asm volatile("st.shared::cluster.f32 [%0], %1;" :: "r"(a), "f"(v) : "memory");
}
static __device__ __forceinline__ void st_cluster4(uint32_t a, float4 v) {
    asm volatile("st.shared::cluster.v4.f32 [%0], {%1,%2,%3,%4};"
                 :: "r"(a), "f"(v.x), "f"(v.y), "f"(v.z), "f"(v.w) : "memory");
}
static __device__ __forceinline__ void mbar_init(uint32_t a, uint32_t cnt) {
    asm volatile("mbarrier.init.shared.b64 [%0], %1;" :: "r"(a), "r"(cnt) : "memory");
}
static __device__ __forceinline__ void mbar_arrive_remote(uint32_t remote_addr) {
    asm volatile("mbarrier.arrive.release.cluster.shared::cluster.b64 _, [%0];"
                 :: "r"(remote_addr) : "memory");
}
static __device__ __forceinline__ void mbar_wait_cluster(uint32_t a, uint32_t ph) {
    asm volatile(
        "{\n\t.reg .pred P;\n\t"
        "WL_%=:\n\t"
        "mbarrier.try_wait.parity.acquire.cluster.shared::cta.b64 P, [%0], %1, 0x989680;\n\t"
        "@P bra.uni WD_%=;\n\t"
        "bra.uni WL_%=;\n\t"
        "WD_%=:\n\t}"
        :: "r"(a), "r"(ph) : "memory");
}
static __device__ __forceinline__ void cluster_sync_all() {
    asm volatile("barrier.cluster.arrive.aligned;" ::: "memory");
    asm volatile("barrier.cluster.wait.aligned;"   ::: "memory");
}

// ---- packed f32x2 helpers (Blackwell FFMA2 — PTX-only) ----
typedef unsigned long long u64t;
struct U2 { u64t lo, hi; };
static __device__ __forceinline__ u64t pack2(float v) {
    u64t r; asm("mov.b64 %0, {%1, %1};" : "=l"(r) : "f"(v)); return r;
}
static __device__ __forceinline__ u64t pack2ab(float a, float b) {
    u64t r; asm("mov.b64 %0, {%1, %2};" : "=l"(r) : "f"(a), "f"(b)); return r;
}
static __device__ __forceinline__ void unpack2(u64t p, float& a, float& b) {
    asm("mov.b64 {%0,%1}, %2;" : "=f"(a), "=f"(b) : "l"(p));
}
static __device__ __forceinline__ void ffma2(u64t& d, u64t a, u64t b) {
    asm("fma.rn.f32x2 %0, %1, %2, %0;" : "+l"(d) : "l"(a), "l"(b));
}
static __device__ __forceinline__ float rcp_fast(float x) {
    float r; asm("rcp.approx.f32 %0, %1;" : "=f"(r) : "f"(x)); return r;
}

struct alignas(16) ClusterSmem {
    float vec[2][C][S];              // double-buffered state vectors, per chunk
    float wsums[2][CL * NW][C];      // per-warp quad-sums, float4 per warp
    unsigned long long full[2];      // mbarrier per buffer, count = CL
};

__global__ void __cluster_dims__(CL, 1, 1) __launch_bounds__(NT, 1)
hmm_scan(const float* __restrict__ obs, const float* __restrict__ A,
         const float* __restrict__ pi0)
{
    __shared__ ClusterSmem sm;

    const int tid = threadIdx.x;
    const int w = tid >> 5;
    const int l = tid & 31;
    const int q = l & 3;                  // lane's chunk role
    const int trank = l >> 2;             // lane's target rank
    const int cluster = (int)blockIdx.x >> 3;
    const bool fwd = (cluster < NCLUS_DIR);
    const int dirIdx = fwd ? cluster : cluster - NCLUS_DIR;
    const uint32_t rank = my_rank();
    const int jbase = (int)rank * SLICE + 4 * w;
    float* gout = fwd ? g_alphas : g_betas;
    const int dir = fwd ? 1 : -1;

    const int chunkid = dirIdx * C + q;
    const int store_lo = chunkid * LCHUNK;
    const bool exact_mine = fwd ? (chunkid == 0) : (chunkid == NCHUNK - 1);
    const int base_mine = exact_mine ? (fwd ? 0 : NSTEP - 1)
                        : (fwd ? store_lo - BURN : store_lo + LCHUNK - 1 + BURN);

    // ---- load A sub-block: 16 rows x 4 cols per thread, packed f32x2 ----
    U2 regA[16];
    if (fwd) {
#pragma unroll
        for (int k = 0; k < 4; k++)
#pragma unroll
            for (int m = 0; m < 4; m++) {
                int i = 128 * k + 4 * l + m;
                float4 t = *reinterpret_cast<const float4*>(A + (size_t)i * S + jbase);
                regA[k * 4 + m].lo = pack2ab(t.x, t.y);
                regA[k * 4 + m].hi = pack2ab(t.z, t.w);
            }
    } else {
#pragma unroll
        for (int k = 0; k < 4; k++)
#pragma unroll
            for (int m = 0; m < 4; m++) {
                int j = 128 * k + 4 * l + m;
                regA[k * 4 + m].lo = pack2ab(A[(size_t)(jbase + 0) * S + j],
                                             A[(size_t)(jbase + 1) * S + j]);
                regA[k * 4 + m].hi = pack2ab(A[(size_t)(jbase + 2) * S + j],
                                             A[(size_t)(jbase + 3) * S + j]);
            }
    }

    // ---- remote DSMEM addresses (lane's (q, trank) role) ----
    const uint32_t va0 = mapa_u32(smem_u32(&sm.vec[0][q][jbase]), trank);
    const uint32_t va1 = mapa_u32(smem_u32(&sm.vec[1][q][jbase]), trank);
    const uint32_t wsa0 = mapa_u32(smem_u32(&sm.wsums[0][rank * NW + w][q]), trank);
    const uint32_t wsa1 = mapa_u32(smem_u32(&sm.wsums[1][rank * NW + w][q]), trank);
    const uint32_t fb0 = mapa_u32(smem_u32(&sm.full[0]), tid & 7);
    const uint32_t fb1 = mapa_u32(smem_u32(&sm.full[1]), tid & 7);
    const uint32_t full0 = smem_u32(&sm.full[0]);
    const uint32_t full1 = smem_u32(&sm.full[1]);

    if (tid == 0) { mbar_init(full0, CL); mbar_init(full1, CL); }
    __syncthreads();
    cluster_sync_all();

    // ---- init step (s=0) ----
    {
        const int t0 = base_mine;
        float4 ob4 = *reinterpret_cast<const float4*>(obs + (size_t)t0 * S + jbase);
        float4 val4;
        if (fwd) {
            if (exact_mine) {
                float4 p4 = *reinterpret_cast<const float4*>(pi0 + jbase);
                val4 = make_float4(p4.x * ob4.x, p4.y * ob4.y, p4.z * ob4.z, p4.w * ob4.w);
                if (l < 4)
                    *reinterpret_cast<float4*>(gout + (size_t)t0 * S + jbase) = val4;
            } else {
                val4 = ob4;
            }
        } else {
            val4 = ob4;
            if (exact_mine && l < 4)
                *reinterpret_cast<float4*>(gout + (size_t)t0 * S + jbase) =
                    make_float4(1.f, 1.f, 1.f, 1.f);
        }
        st_cluster4(va0, val4);
        st_cluster(wsa0, (val4.x + val4.y) + (val4.z + val4.w));
        __syncthreads();
        if (tid < 8) mbar_arrive_remote(fb0);
    }

    float4 ob_cur = *reinterpret_cast<const float4*>(
        obs + (size_t)(base_mine + dir) * S + jbase);

    // ---- recurrence: 575 steps, chunks processed SEQUENTIALLY per step ----
    for (int s = 1; s <= NSTEPS_LOOP; ++s) {
        const int p = (s - 1) & 1;
        const uint32_t ph = (uint32_t)((s - 1) >> 1) & 1u;
        const int t_prod = base_mine + dir * s;

        float4 ob_nxt = ob_cur;
        if (s + 1 <= NSTEPS_LOOP)
            ob_nxt = *reinterpret_cast<const float4*>(
                obs + (size_t)(t_prod + dir) * S + jbase);

        mbar_wait_cluster(p ? full1 : full0, ph);

        // totals of previous broadcast per chunk (128 float4 warp entries)
        const float4* wb = reinterpret_cast<const float4*>(&sm.wsums[p][0][0]);
        float4 w0 = wb[4 * l + 0], w1 = wb[4 * l + 1];
        float4 w2 = wb[4 * l + 2], w3 = wb[4 * l + 3];
        float4 wp = make_float4((w0.x + w1.x) + (w2.x + w3.x),
                                (w0.y + w1.y) + (w2.y + w3.y),
                                (w0.z + w1.z) + (w2.z + w3.z),
                                (w0.w + w1.w) + (w2.w + w3.w));
#pragma unroll
        for (int o = 16; o >= 1; o >>= 1) {
            wp.x += __shfl_xor_sync(~0u, wp.x, o);
            wp.y += __shfl_xor_sync(~0u, wp.y, o);
            wp.z += __shfl_xor_sync(~0u, wp.z, o);
            wp.w += __shfl_xor_sync(~0u, wp.w, o);
        }

        const float4* vb = reinterpret_cast<const float4*>(&sm.vec[p][0][0]);
        const uint32_t va = (s & 1) ? va1 : va0;
        const uint32_t wsa = (s & 1) ? wsa1 : wsa0;
        const bool store_ok = exact_mine ? (s <= LCHUNK - 1) : (s >= BURN);

        // ---- chunks one at a time: registers reused, no spills ----
#pragma unroll
        for (int cc = 0; cc < C; cc++) {
            u64t alo = 0ull, ahi = 0ull;
#pragma unroll
            for (int k = 0; k < 4; k++) {
                float4 v4 = vb[cc * 128 + 32 * k + l];
                u64t vx = pack2(v4.x), vy = pack2(v4.y);
                u64t vz = pack2(v4.z), vw = pack2(v4.w);
                ffma2(alo, vx, regA[k * 4 + 0].lo); ffma2(ahi, vx, regA[k * 4 + 0].hi);
                ffma2(alo, vy, regA[k * 4 + 1].lo); ffma2(ahi, vy, regA[k * 4 + 1].hi);
                ffma2(alo, vz, regA[k * 4 + 2].lo); ffma2(ahi, vz, regA[k * 4 + 2].hi);
                ffma2(alo, vw, regA[k * 4 + 3].lo); ffma2(ahi, vw, regA[k * 4 + 3].hi);
            }
            float a0, a1, a2, a3;
            unpack2(alo, a0, a1);
            unpack2(ahi, a2, a3);
#pragma unroll
            for (int o = 16; o >= 1; o >>= 1) {
                a0 += __shfl_xor_sync(~0u, a0, o);
                a1 += __shfl_xor_sync(~0u, a1, o);
                a2 += __shfl_xor_sync(~0u, a2, o);
                a3 += __shfl_xor_sync(~0u, a3, o);
            }
            // every lane holds chunk cc's 4 column totals
            const float invc = rcp_fast(cc == 0 ? wp.x : cc == 1 ? wp.y
                                       : cc == 2 ? wp.z : wp.w);
            float4 dv4 = make_float4(invc * a0, invc * a1, invc * a2, invc * a3);

            if (q == cc) {   // 8 lanes: this chunk's broadcast + store role
                float4 val4 = make_float4(dv4.x * ob_cur.x, dv4.y * ob_cur.y,
                                          dv4.z * ob_cur.z, dv4.w * ob_cur.w);
                if (s < NSTEPS_LOOP) {
                    st_cluster4(va, val4);
                    st_cluster(wsa, (val4.x + val4.y) + (val4.z + val4.w));
                }
                if (l == cc && store_ok)
                    *reinterpret_cast<float4*>(gout + (size_t)t_prod * S + jbase) =
                        fwd ? val4 : dv4;
            }
        }

        if (s < NSTEPS_LOOP) {
            __syncthreads();
            if (tid < 8) mbar_arrive_remote((s & 1) ? fb1 : fb0);
        }
        ob_cur = ob_nxt;
    }
    cluster_sync_all();
}

// gamma_t = (alpha_t * beta_t) / rowsum — one warp per timestep
__global__ void __launch_bounds__(256) gamma_kernel(float* __restrict__ out)
{
    const int row = (int)((blockIdx.x * 256 + threadIdx.x) >> 5);
    const int l = threadIdx.x & 31;
    const float4* a4 = reinterpret_cast<const float4*>(g_alphas + (size_t)row * S);
    const float4* b4 = reinterpret_cast<const float4*>(g_betas  + (size_t)row * S);
    float4 pr[4];
    float s = 0.f;
#pragma unroll
    for (int k = 0; k < 4; k++) {
        float4 a = a4[k * 32 + l];
        float4 b = b4[k * 32 + l];
        float4 qv = make_float4(a.x * b.x, a.y * b.y, a.z * b.z, a.w * b.w);
        pr[k] = qv;
        s += (qv.x + qv.y) + (qv.z + qv.w);
    }
#pragma unroll
    for (int o = 16; o >= 1; o >>= 1) s += __shfl_xor_sync(~0u, s, o);
    const float inv = 1.0f / s;
    float4* o4 = reinterpret_cast<float4*>(out + (size_t)row * S);
#pragma unroll
    for (int k = 0; k < 4; k++) {
        float4 qv = pr[k];
        o4[k * 32 + l] = make_float4(qv.x * inv, qv.y * inv, qv.z * inv, qv.w * inv);
    }
}

extern "C" void kernel_launch(void* const* d_in, const int* in_sizes, int n_in,
                              void* d_out, int out_size)
{
    const float* obs = (const float*)d_in[0];   // [NSTEP, S]
    const float* A   = (const float*)d_in[1];   // [S, S]
    const float* pi0 = (const float*)d_in[2];   // [S]
    (void)in_sizes; (void)n_in; (void)out_size;

    hmm_scan<<<2 * NCLUS_DIR * CL, NT>>>(obs, A, pi0);
    gamma_kernel<<<(NSTEP * 32) / 256, 256>>>((float*)d_out);
}

// round 9
// speedup vs baseline: 1.8352x; 1.8352x over previous
#include <cuda_runtime.h>
#include <cstdint>
#include <cstddef>

#define NSTEP 16384
#define S     512
#define CL    8            // CTAs per cluster
#define NCLUS_DIR 8        // clusters per direction
#define C     4            // chunks per cluster
#define NCHUNK (NCLUS_DIR * C)          // 32 chunks per direction
#define LCHUNK (NSTEP / NCHUNK)         // 512
#define BURN  64
#define SLICE 64
#define NT    512
#define NSTEPS_LOOP (LCHUNK - 1 + BURN) // 575
#define VBUF_BYTES (C * S * 4)          // 8192: offset between vec buffers

__device__ float g_alphas[(size_t)NSTEP * S];
__device__ float g_betas[(size_t)NSTEP * S];

static __device__ __forceinline__ uint32_t smem_u32(const void* p) {
    uint32_t a;
    asm("{ .reg .u64 t; cvta.to.shared.u64 t, %1; cvt.u32.u64 %0, t; }"
        : "=r"(a) : "l"(p));
    return a;
}
static __device__ __forceinline__ uint32_t my_rank() {
    uint32_t r; asm("mov.u32 %0, %%cluster_ctarank;" : "=r"(r)); return r;
}
static __device__ __forceinline__ uint32_t mapa_u32(uint32_t a, uint32_t rank) {
    uint32_t r;
    asm("mapa.shared::cluster.u32 %0, %1, %2;" : "=r"(r) : "r"(a), "r"(rank));
    return r;
}
static __device__ __forceinline__ void st_cluster(uint32_t a, float v) {
    asm volatile("st.shared::cluster.f32 [%0], %1;" :: "r"(a), "f"(v) : "memory");
}
static __device__ __forceinline__ void mbar_init(uint32_t a, uint32_t cnt) {
    asm volatile("mbarrier.init.shared.b64 [%0], %1;" :: "r"(a), "r"(cnt) : "memory");
}
static __device__ __forceinline__ void mbar_arrive_remote(uint32_t remote_addr) {
    asm volatile("mbarrier.arrive.release.cluster.shared::cluster.b64 _, [%0];"
                 :: "r"(remote_addr) : "memory");
}
static __device__ __forceinline__ void mbar_wait_cluster(uint32_t a, uint32_t ph) {
    asm volatile(
        "{\n\t.reg .pred P;\n\t"
        "WL_%=:\n\t"
        "mbarrier.try_wait.parity.acquire.cluster.shared::cta.b64 P, [%0], %1, 0x989680;\n\t"
        "@P bra.uni WD_%=;\n\t"
        "bra.uni WL_%=;\n\t"
        "WD_%=:\n\t}"
        :: "r"(a), "r"(ph) : "memory");
}
static __device__ __forceinline__ void cluster_sync_all() {
    asm volatile("barrier.cluster.arrive.aligned;" ::: "memory");
    asm volatile("barrier.cluster.wait.aligned;"   ::: "memory");
}

// ---- packed f32x2 helpers (Blackwell FFMA2 — PTX-only) ----
typedef unsigned long long u64t;
struct U2 { u64t lo, hi; };
static __device__ __forceinline__ u64t pack2(float v) {
    u64t r; asm("mov.b64 %0, {%1, %1};" : "=l"(r) : "f"(v)); return r;
}
static __device__ __forceinline__ u64t pack2ab(float a, float b) {
    u64t r; asm("mov.b64 %0, {%1, %2};" : "=l"(r) : "f"(a), "f"(b)); return r;
}
static __device__ __forceinline__ void unpack2(u64t p, float& a, float& b) {
    asm("mov.b64 {%0,%1}, %2;" : "=f"(a), "=f"(b) : "l"(p));
}
static __device__ __forceinline__ void ffma2(u64t& d, u64t a, u64t b) {
    asm("fma.rn.f32x2 %0, %1, %2, %0;" : "+l"(d) : "l"(a), "l"(b));
}
static __device__ __forceinline__ float rcp_fast(float x) {
    float r; asm("rcp.approx.f32 %0, %1;" : "=f"(r) : "f"(x)); return r;
}

struct alignas(16) ClusterSmem {
    float vec[2][C][S];              // double-buffered state vectors, per chunk
    unsigned long long full[2];      // mbarrier per buffer, count = CL
};

__global__ void __cluster_dims__(CL, 1, 1) __launch_bounds__(NT, 1)
hmm_scan(const float* __restrict__ obs, const float* __restrict__ A,
         const float* __restrict__ pi0)
{
    __shared__ ClusterSmem sm;

    const int tid = threadIdx.x;
    const int w = tid >> 5;
    const int l = tid & 31;
    const int c = (l >> 2) & 3;           // lane's chunk
    const int mcol = l & 3;               // lane's column within warp quad
    const int cluster = (int)blockIdx.x >> 3;
    const bool fwd = (cluster < NCLUS_DIR);
    const int dirIdx = fwd ? cluster : cluster - NCLUS_DIR;
    const uint32_t rank = my_rank();
    const int jbase = (int)rank * SLICE + 4 * w;
    const int jcol = jbase + mcol;
    float* gout = fwd ? g_alphas : g_betas;
    const int dir = fwd ? 1 : -1;

    const int chunkid = dirIdx * C + c;
    const int store_lo = chunkid * LCHUNK;
    const bool exact_mine = fwd ? (chunkid == 0) : (chunkid == NCHUNK - 1);
    const int base_mine = exact_mine ? (fwd ? 0 : NSTEP - 1)
                        : (fwd ? store_lo - BURN : store_lo + LCHUNK - 1 + BURN);

    // ---- load A sub-block: 16 rows x 4 cols per thread, packed f32x2 ----
    U2 regA[16];
    if (fwd) {
#pragma unroll
        for (int k = 0; k < 4; k++)
#pragma unroll
            for (int m = 0; m < 4; m++) {
                int i = 128 * k + 4 * l + m;
                float4 t = *reinterpret_cast<const float4*>(A + (size_t)i * S + jbase);
                regA[k * 4 + m].lo = pack2ab(t.x, t.y);
                regA[k * 4 + m].hi = pack2ab(t.z, t.w);
            }
    } else {
#pragma unroll
        for (int k = 0; k < 4; k++)
#pragma unroll
            for (int m = 0; m < 4; m++) {
                int j = 128 * k + 4 * l + m;
                regA[k * 4 + m].lo = pack2ab(A[(size_t)(jbase + 0) * S + j],
                                             A[(size_t)(jbase + 1) * S + j]);
                regA[k * 4 + m].hi = pack2ab(A[(size_t)(jbase + 2) * S + j],
                                             A[(size_t)(jbase + 3) * S + j]);
            }
    }

    // ---- remote DSMEM addresses (buffer 0; buffer 1 = +VBUF_BYTES) ----
    // lane stores its scalar result (chunk c, column jcol) to 4 target ranks
    const int tr_base = (l >> 4) << 2;    // lanes 0-15 -> ranks 0-3, 16-31 -> 4-7
    uint32_t va[4];
#pragma unroll
    for (int r = 0; r < 4; r++)
        va[r] = mapa_u32(smem_u32(&sm.vec[0][c][jcol]), tr_base + r);
    const uint32_t fb0   = mapa_u32(smem_u32(&sm.full[0]), tid & 7);
    const uint32_t full0 = smem_u32(&sm.full[0]);
    const uint32_t den0  = smem_u32(&sm.vec[0][c][0]);

    if (tid == 0) { mbar_init(full0, CL); mbar_init(full0 + 8, CL); }
    __syncthreads();
    cluster_sync_all();

    // ---- init step (s=0): buffer 0 ----
    {
        const int t0 = base_mine;
        float ob0 = obs[(size_t)t0 * S + jcol];
        float val;
        if (fwd) {
            if (exact_mine) {
                val = pi0[jcol] * ob0;
                if (l < 16) gout[(size_t)t0 * S + jcol] = val;
            } else val = ob0;
        } else {
            val = ob0;
            if (exact_mine && l < 16) gout[(size_t)t0 * S + jcol] = 1.0f;
        }
#pragma unroll
        for (int r = 0; r < 4; r++) st_cluster(va[r], val);
        __syncthreads();
        if (tid < 8) mbar_arrive_remote(fb0);
    }

    float ob_cur = obs[(size_t)(base_mine + dir) * S + jcol];

    // ---- recurrence: 575 steps ----
    for (int s = 1; s <= NSTEPS_LOOP; ++s) {
        const int p = (s - 1) & 1;
        const uint32_t ph = (uint32_t)((s - 1) >> 1) & 1u;
        const int t_prod = base_mine + dir * s;

        float ob_nxt = ob_cur;
        if (s + 1 <= NSTEPS_LOOP)
            ob_nxt = obs[(size_t)(t_prod + dir) * S + jcol];

        mbar_wait_cluster(full0 + (p ? 8u : 0u), ph);

        // normalization scalar: element 0 of received vector for lane's chunk
        float den;
        asm volatile("ld.shared.f32 %0, [%1];" : "=f"(den)
                     : "r"(den0 + (uint32_t)(p ? VBUF_BYTES : 0)));
        const float inv = rcp_fast(den);

        // matvec: 4 chunks sequential into accf[16]  (vi = c*4 + m)
        const float4* vb = reinterpret_cast<const float4*>(&sm.vec[p][0][0]);
        float v[16];
#pragma unroll
        for (int cc = 0; cc < C; cc++) {
            u64t alo = 0ull, ahi = 0ull;
#pragma unroll
            for (int k = 0; k < 4; k++) {
                float4 v4 = vb[cc * 128 + 32 * k + l];
                u64t vx = pack2(v4.x), vy = pack2(v4.y);
                u64t vz = pack2(v4.z), vw = pack2(v4.w);
                ffma2(alo, vx, regA[k * 4 + 0].lo); ffma2(ahi, vx, regA[k * 4 + 0].hi);
                ffma2(alo, vy, regA[k * 4 + 1].lo); ffma2(ahi, vy, regA[k * 4 + 1].hi);
                ffma2(alo, vz, regA[k * 4 + 2].lo); ffma2(ahi, vz, regA[k * 4 + 2].hi);
                ffma2(alo, vw, regA[k * 4 + 3].lo); ffma2(ahi, vw, regA[k * 4 + 3].hi);
            }
            unpack2(alo, v[cc * 4 + 0], v[cc * 4 + 1]);
            unpack2(ahi, v[cc * 4 + 2], v[cc * 4 + 3]);
        }

        // value-compaction reduction: 16 values over 32 lanes in 16 SHFLs.
        // After stages, lane l holds the total for vi = l & 15.
#pragma unroll
        for (int mm = 8; mm >= 1; mm >>= 1) {
            const bool up = (l & mm);
#pragma unroll
            for (int si = 0; si < mm; si++) {
                float keep = up ? v[si + mm] : v[si];
                float send = up ? v[si] : v[si + mm];
                v[si] = keep + __shfl_xor_sync(~0u, send, mm);
            }
        }
        v[0] += __shfl_xor_sync(~0u, v[0], 16);
        // lane l: total for (chunk c=(l&15)>>2, column jcol) — matches roles

        const float dv  = v[0] * inv;
        const float val = dv * ob_cur;

        const bool store_ok = exact_mine ? (s <= LCHUNK - 1) : (s >= BURN);
        if (l < 16 && store_ok)
            gout[(size_t)t_prod * S + jcol] = fwd ? val : dv;

        if (s < NSTEPS_LOOP) {
            const uint32_t bo = (s & 1) ? (uint32_t)VBUF_BYTES : 0u;
#pragma unroll
            for (int r = 0; r < 4; r++) st_cluster(va[r] + bo, val);
            __syncthreads();
            if (tid < 8) mbar_arrive_remote(fb0 + ((s & 1) ? 8u : 0u));
        }
        ob_cur = ob_nxt;
    }
    cluster_sync_all();
}

// gamma_t = (alpha_t * beta_t) / rowsum — one warp per timestep
__global__ void __launch_bounds__(256) gamma_kernel(float* __restrict__ out)
{
    const int row = (int)((blockIdx.x * 256 + threadIdx.x) >> 5);
    const int l = threadIdx.x & 31;
    const float4* a4 = reinterpret_cast<const float4*>(g_alphas + (size_t)row * S);
    const float4* b4 = reinterpret_cast<const float4*>(g_betas  + (size_t)row * S);
    float4 pr[4];
    float s = 0.f;
#pragma unroll
    for (int k = 0; k < 4; k++) {
        float4 a = a4[k * 32 + l];
        float4 b = b4[k * 32 + l];
        float4 qv = make_float4(a.x * b.x, a.y * b.y, a.z * b.z, a.w * b.w);
        pr[k] = qv;
        s += (qv.x + qv.y) + (qv.z + qv.w);
    }
#pragma unroll
    for (int o = 16; o >= 1; o >>= 1) s += __shfl_xor_sync(~0u, s, o);
    const float inv = 1.0f / s;
    float4* o4 = reinterpret_cast<float4*>(out + (size_t)row * S);
#pragma unroll
    for (int k = 0; k < 4; k++) {
        float4 qv = pr[k];
        o4[k * 32 + l] = make_float4(qv.x * inv, qv.y * inv, qv.z * inv, qv.w * inv);
    }
}

extern "C" void kernel_launch(void* const* d_in, const int* in_sizes, int n_in,
                              void* d_out, int out_size)
{
    const float* obs = (const float*)d_in[0];   // [NSTEP, S]
    const float* A   = (const float*)d_in[1];   // [S, S]
    const float* pi0 = (const float*)d_in[2];   // [S]
    (void)in_sizes; (void)n_in; (void)out_size;

    hmm_scan<<<2 * NCLUS_DIR * CL, NT>>>(obs, A, pi0);
    gamma_kernel<<<(NSTEP * 32) / 256, 256>>>((float*)d_out);
}

// round 10
// speedup vs baseline: 1.8433x; 1.0044x over previous
#include <cuda_runtime.h>
#include <cstdint>
#include <cstddef>

#define NSTEP 16384
#define S     512
#define CL    8            // CTAs per cluster
#define NCLUS_DIR 8        // clusters per direction
#define C     8            // chunks per cluster (2 groups of 4)
#define NCHUNK (NCLUS_DIR * C)          // 64 chunks per direction
#define LCHUNK (NSTEP / NCHUNK)         // 256
#define BURN  64
#define SLICE 64
#define NT    512
#define NSTEPS_LOOP (LCHUNK - 1 + BURN) // 319
#define CHUNK_BYTES (S * 4)             // 2048: one chunk's vector
#define GRP_BYTES  (4 * CHUNK_BYTES)    // 8192: group 0 -> group 1 offset
#define VBUF_BYTES (C * CHUNK_BYTES)    // 16384: buffer 0 -> buffer 1 offset

__device__ float g_alphas[(size_t)NSTEP * S];
__device__ float g_betas[(size_t)NSTEP * S];

static __device__ __forceinline__ uint32_t smem_u32(const void* p) {
    uint32_t a;
    asm("{ .reg .u64 t; cvta.to.shared.u64 t, %1; cvt.u32.u64 %0, t; }"
        : "=r"(a) : "l"(p));
    return a;
}
static __device__ __forceinline__ uint32_t my_rank() {
    uint32_t r; asm("mov.u32 %0, %%cluster_ctarank;" : "=r"(r)); return r;
}
static __device__ __forceinline__ uint32_t mapa_u32(uint32_t a, uint32_t rank) {
    uint32_t r;
    asm("mapa.shared::cluster.u32 %0, %1, %2;" : "=r"(r) : "r"(a), "r"(rank));
    return r;
}
static __device__ __forceinline__ void st_cluster(uint32_t a, float v) {
    asm volatile("st.shared::cluster.f32 [%0], %1;" :: "r"(a), "f"(v) : "memory");
}
static __device__ __forceinline__ void mbar_init(uint32_t a, uint32_t cnt) {
    asm volatile("mbarrier.init.shared.b64 [%0], %1;" :: "r"(a), "r"(cnt) : "memory");
}
static __device__ __forceinline__ void mbar_arrive_remote(uint32_t remote_addr) {
    asm volatile("mbarrier.arrive.release.cluster.shared::cluster.b64 _, [%0];"
                 :: "r"(remote_addr) : "memory");
}
static __device__ __forceinline__ void mbar_wait_cluster(uint32_t a, uint32_t ph) {
    asm volatile(
        "{\n\t.reg .pred P;\n\t"
        "WL_%=:\n\t"
        "mbarrier.try_wait.parity.acquire.cluster.shared::cta.b64 P, [%0], %1, 0x989680;\n\t"
        "@P bra.uni WD_%=;\n\t"
        "bra.uni WL_%=;\n\t"
        "WD_%=:\n\t}"
        :: "r"(a), "r"(ph) : "memory");
}
static __device__ __forceinline__ void cluster_sync_all() {
    asm volatile("barrier.cluster.arrive.aligned;" ::: "memory");
    asm volatile("barrier.cluster.wait.aligned;"   ::: "memory");
}

// ---- packed f32x2 helpers (Blackwell FFMA2 — PTX-only) ----
typedef unsigned long long u64t;
struct U2 { u64t lo, hi; };
static __device__ __forceinline__ u64t pack2(float v) {
    u64t r; asm("mov.b64 %0, {%1, %1};" : "=l"(r) : "f"(v)); return r;
}
static __device__ __forceinline__ u64t pack2ab(float a, float b) {
    u64t r; asm("mov.b64 %0, {%1, %2};" : "=l"(r) : "f"(a), "f"(b)); return r;
}
static __device__ __forceinline__ void unpack2(u64t p, float& a, float& b) {
    asm("mov.b64 {%0,%1}, %2;" : "=f"(a), "=f"(b) : "l"(p));
}
static __device__ __forceinline__ void ffma2(u64t& d, u64t a, u64t b) {
    asm("fma.rn.f32x2 %0, %1, %2, %0;" : "+l"(d) : "l"(a), "l"(b));
}
static __device__ __forceinline__ float rcp_fast(float x) {
    float r; asm("rcp.approx.f32 %0, %1;" : "=f"(r) : "f"(x)); return r;
}

struct alignas(16) ClusterSmem {
    float vec[2][C][S];              // double-buffered state vectors, per chunk
    unsigned long long full[2];      // mbarrier per buffer, count = CL*NW = 128
};

__global__ void __cluster_dims__(CL, 1, 1) __launch_bounds__(NT, 1)
hmm_scan(const float* __restrict__ obs, const float* __restrict__ A,
         const float* __restrict__ pi0)
{
    __shared__ ClusterSmem sm;

    const int tid = threadIdx.x;
    const int w = tid >> 5;
    const int l = tid & 31;
    const int ccg = (l >> 2) & 3;         // lane's chunk-within-group
    const int mcol = l & 3;               // lane's column within warp quad
    const int cluster = (int)blockIdx.x >> 3;
    const bool fwd = (cluster < NCLUS_DIR);
    const int dirIdx = fwd ? cluster : cluster - NCLUS_DIR;
    const uint32_t rank = my_rank();
    const int jbase = (int)rank * SLICE + 4 * w;
    const int jcol = jbase + mcol;
    float* gout = fwd ? g_alphas : g_betas;
    const int dir = fwd ? 1 : -1;

    // per-lane chunk params for its two chunks (group 0 and group 1)
    int base_g[2]; bool exact_g[2];
#pragma unroll
    for (int g = 0; g < 2; g++) {
        const int chunkid = dirIdx * C + g * 4 + ccg;
        const int store_lo = chunkid * LCHUNK;
        const bool ex = fwd ? (chunkid == 0) : (chunkid == NCHUNK - 1);
        exact_g[g] = ex;
        base_g[g] = ex ? (fwd ? 0 : NSTEP - 1)
                       : (fwd ? store_lo - BURN : store_lo + LCHUNK - 1 + BURN);
    }

    // ---- load A sub-block: 16 rows x 4 cols per thread, packed f32x2 ----
    U2 regA[16];
    if (fwd) {
#pragma unroll
        for (int k = 0; k < 4; k++)
#pragma unroll
            for (int m = 0; m < 4; m++) {
                int i = 128 * k + 4 * l + m;
                float4 t = *reinterpret_cast<const float4*>(A + (size_t)i * S + jbase);
                regA[k * 4 + m].lo = pack2ab(t.x, t.y);
                regA[k * 4 + m].hi = pack2ab(t.z, t.w);
            }
    } else {
#pragma unroll
        for (int k = 0; k < 4; k++)
#pragma unroll
            for (int m = 0; m < 4; m++) {
                int j = 128 * k + 4 * l + m;
                regA[k * 4 + m].lo = pack2ab(A[(size_t)(jbase + 0) * S + j],
                                             A[(size_t)(jbase + 1) * S + j]);
                regA[k * 4 + m].hi = pack2ab(A[(size_t)(jbase + 2) * S + j],
                                             A[(size_t)(jbase + 3) * S + j]);
            }
    }

    // ---- remote DSMEM addresses for group 0 (group 1 = +GRP_BYTES,
    //      buffer 1 = +VBUF_BYTES) ----
    const int tr_base = (l >> 4) << 2;    // lanes 0-15 -> ranks 0-3, 16-31 -> 4-7
    uint32_t va[4];
#pragma unroll
    for (int r = 0; r < 4; r++)
        va[r] = mapa_u32(smem_u32(&sm.vec[0][ccg][jcol]), tr_base + r);
    const uint32_t fb    = mapa_u32(smem_u32(&sm.full[0]), l & 7);  // lanes 0-7
    const uint32_t full0 = smem_u32(&sm.full[0]);
    const uint32_t den0  = smem_u32(&sm.vec[0][ccg][0]);

    if (tid == 0) { mbar_init(full0, CL * 16); mbar_init(full0 + 8, CL * 16); }
    __syncthreads();
    cluster_sync_all();

    // ---- init step (s=0): buffer 0, both groups ----
    {
#pragma unroll
        for (int g = 0; g < 2; g++) {
            const int t0 = base_g[g];
            float ob0 = obs[(size_t)t0 * S + jcol];
            float val;
            if (fwd) {
                if (exact_g[g]) {
                    val = pi0[jcol] * ob0;
                    if (l < 16) gout[(size_t)t0 * S + jcol] = val;
                } else val = ob0;
            } else {
                val = ob0;
                if (exact_g[g] && l < 16) gout[(size_t)t0 * S + jcol] = 1.0f;
            }
            const uint32_t go = (uint32_t)(g * GRP_BYTES);
#pragma unroll
            for (int r = 0; r < 4; r++) st_cluster(va[r] + go, val);
        }
        __syncwarp();
        if (l < 8) mbar_arrive_remote(fb);
    }

    float ob_cur[2];
#pragma unroll
    for (int g = 0; g < 2; g++)
        ob_cur[g] = obs[(size_t)(base_g[g] + dir) * S + jcol];

    // ---- recurrence: 319 steps, 8 chunks each (2 groups of 4) ----
    for (int s = 1; s <= NSTEPS_LOOP; ++s) {
        const int p = (s - 1) & 1;
        const uint32_t ph = (uint32_t)((s - 1) >> 1) & 1u;
        const uint32_t pb = p ? (uint32_t)VBUF_BYTES : 0u;   // read-buffer offset
        const uint32_t sb = (s & 1) ? (uint32_t)VBUF_BYTES : 0u; // write-buffer off

        // prefetch next obs for both groups (issues before the wait)
        float ob_nxt[2] = {ob_cur[0], ob_cur[1]};
        if (s + 1 <= NSTEPS_LOOP) {
#pragma unroll
            for (int g = 0; g < 2; g++)
                ob_nxt[g] = obs[(size_t)(base_g[g] + dir * (s + 1)) * S + jcol];
        }

        mbar_wait_cluster(full0 + (p ? 8u : 0u), ph);

        const float4* vb = reinterpret_cast<const float4*>(
            reinterpret_cast<const char*>(&sm.vec[0][0][0]) + pb);

#pragma unroll
        for (int g = 0; g < 2; g++) {
            // normalization scalar: element 0 of this lane's chunk vector
            float den;
            asm volatile("ld.shared.f32 %0, [%1];" : "=f"(den)
                         : "r"(den0 + pb + (uint32_t)(g * GRP_BYTES)));
            const float inv = rcp_fast(den);

            // matvec for group's 4 chunks -> v[16]  (vi = cc*4 + m)
            float v[16];
#pragma unroll
            for (int cc = 0; cc < 4; cc++) {
                u64t alo = 0ull, ahi = 0ull;
#pragma unroll
                for (int k = 0; k < 4; k++) {
                    float4 v4 = vb[(g * 4 + cc) * 128 + 32 * k + l];
                    u64t vx = pack2(v4.x), vy = pack2(v4.y);
                    u64t vz = pack2(v4.z), vw = pack2(v4.w);
                    ffma2(alo, vx, regA[k * 4 + 0].lo); ffma2(ahi, vx, regA[k * 4 + 0].hi);
                    ffma2(alo, vy, regA[k * 4 + 1].lo); ffma2(ahi, vy, regA[k * 4 + 1].hi);
                    ffma2(alo, vz, regA[k * 4 + 2].lo); ffma2(ahi, vz, regA[k * 4 + 2].hi);
                    ffma2(alo, vw, regA[k * 4 + 3].lo); ffma2(ahi, vw, regA[k * 4 + 3].hi);
                }
                unpack2(alo, v[cc * 4 + 0], v[cc * 4 + 1]);
                unpack2(ahi, v[cc * 4 + 2], v[cc * 4 + 3]);
            }

            // value-compaction reduction: lane l ends with total for vi = l&15
#pragma unroll
            for (int mm = 8; mm >= 1; mm >>= 1) {
                const bool up = (l & mm);
#pragma unroll
                for (int si = 0; si < mm; si++) {
                    float keep = up ? v[si + mm] : v[si];
                    float send = up ? v[si] : v[si + mm];
                    v[si] = keep + __shfl_xor_sync(~0u, send, mm);
                }
            }
            v[0] += __shfl_xor_sync(~0u, v[0], 16);

            const float dv  = v[0] * inv;
            const float val = dv * ob_cur[g];
            const int t_prod = base_g[g] + dir * s;
            const bool store_ok = exact_g[g] ? (s <= LCHUNK - 1) : (s >= BURN);
            if (l < 16 && store_ok)
                gout[(size_t)t_prod * S + jcol] = fwd ? val : dv;

            if (s < NSTEPS_LOOP) {
                const uint32_t go = sb + (uint32_t)(g * GRP_BYTES);
#pragma unroll
                for (int r = 0; r < 4; r++) st_cluster(va[r] + go, val);
            }
            ob_cur[g] = ob_nxt[g];
        }

        // per-warp arrive: warp-scope ordering, then lanes 0-7 hit all 8 ranks
        if (s < NSTEPS_LOOP) {
            __syncwarp();
            if (l < 8) mbar_arrive_remote(fb + ((s & 1) ? 8u : 0u));
        }
    }
    cluster_sync_all();   // keep smem alive until all remote traffic lands
}

// gamma_t = (alpha_t * beta_t) / rowsum — one warp per timestep
__global__ void __launch_bounds__(256) gamma_kernel(float* __restrict__ out)
{
    const int row = (int)((blockIdx.x * 256 + threadIdx.x) >> 5);
    const int l = threadIdx.x & 31;
    const float4* a4 = reinterpret_cast<const float4*>(g_alphas + (size_t)row * S);
    const float4* b4 = reinterpret_cast<const float4*>(g_betas  + (size_t)row * S);
    float4 pr[4];
    float s = 0.f;
#pragma unroll
    for (int k = 0; k < 4; k++) {
        float4 a = a4[k * 32 + l];
        float4 b = b4[k * 32 + l];
        float4 qv = make_float4(a.x * b.x, a.y * b.y, a.z * b.z, a.w * b.w);
        pr[k] = qv;
        s += (qv.x + qv.y) + (qv.z + qv.w);
    }
#pragma unroll
    for (int o = 16; o >= 1; o >>= 1) s += __shfl_xor_sync(~0u, s, o);
    const float inv = 1.0f / s;
    float4* o4 = reinterpret_cast<float4*>(out + (size_t)row * S);
#pragma unroll
    for (int k = 0; k < 4; k++) {
        float4 qv = pr[k];
        o4[k * 32 + l] = make_float4(qv.x * inv, qv.y * inv, qv.z * inv, qv.w * inv);
    }
}

extern "C" void kernel_launch(void* const* d_in, const int* in_sizes, int n_in,
                              void* d_out, int out_size)
{
    const float* obs = (const float*)d_in[0];   // [NSTEP, S]
    const float* A   = (const float*)d_in[1];   // [S, S]
    const float* pi0 = (const float*)d_in[2];   // [S]
    (void)in_sizes; (void)n_in; (void)out_size;

    hmm_scan<<<2 * NCLUS_DIR * CL, NT>>>(obs, A, pi0);
    gamma_kernel<<<(NSTEP * 32) / 256, 256>>>((float*)d_out);
}

// round 11
// speedup vs baseline: 2.0127x; 1.0919x over previous
#include <cuda_runtime.h>
#include <cstdint>
#include <cstddef>

#define NSTEP 16384
#define S     512
#define CL    8            // CTAs per cluster
#define NCLUS_DIR 8        // clusters per direction
#define C     8            // chunks per cluster (2 groups of 4)
#define NCHUNK (NCLUS_DIR * C)          // 64 chunks per direction
#define LCHUNK (NSTEP / NCHUNK)         // 256
#define BURN  32
#define SLICE 64
#define NT    512
#define NSTEPS_LOOP (LCHUNK - 1 + BURN) // 287
#define CHUNK_BYTES (S * 4)             // 2048
#define GRP_BYTES  (4 * CHUNK_BYTES)    // 8192
#define VBUF_BYTES (C * CHUNK_BYTES)    // 16384

__device__ float g_alphas[(size_t)NSTEP * S];
__device__ float g_betas[(size_t)NSTEP * S];

static __device__ __forceinline__ uint32_t smem_u32(const void* p) {
    uint32_t a;
    asm("{ .reg .u64 t; cvta.to.shared.u64 t, %1; cvt.u32.u64 %0, t; }"
        : "=r"(a) : "l"(p));
    return a;
}
static __device__ __forceinline__ uint32_t my_rank() {
    uint32_t r; asm("mov.u32 %0, %%cluster_ctarank;" : "=r"(r)); return r;
}
static __device__ __forceinline__ uint32_t mapa_u32(uint32_t a, uint32_t rank) {
    uint32_t r;
    asm("mapa.shared::cluster.u32 %0, %1, %2;" : "=r"(r) : "r"(a), "r"(rank));
    return r;
}
static __device__ __forceinline__ void st_cluster(uint32_t a, float v) {
    asm volatile("st.shared::cluster.f32 [%0], %1;" :: "r"(a), "f"(v) : "memory");
}
static __device__ __forceinline__ void mbar_init(uint32_t a, uint32_t cnt) {
    asm volatile("mbarrier.init.shared.b64 [%0], %1;" :: "r"(a), "r"(cnt) : "memory");
}
static __device__ __forceinline__ void mbar_arrive_remote(uint32_t remote_addr) {
    asm volatile("mbarrier.arrive.release.cluster.shared::cluster.b64 _, [%0];"
                 :: "r"(remote_addr) : "memory");
}
static __device__ __forceinline__ void mbar_wait_cluster(uint32_t a, uint32_t ph) {
    asm volatile(
        "{\n\t.reg .pred P;\n\t"
        "WL_%=:\n\t"
        "mbarrier.try_wait.parity.acquire.cluster.shared::cta.b64 P, [%0], %1, 0x989680;\n\t"
        "@P bra.uni WD_%=;\n\t"
        "bra.uni WL_%=;\n\t"
        "WD_%=:\n\t}"
        :: "r"(a), "r"(ph) : "memory");
}
static __device__ __forceinline__ void cluster_sync_all() {
    asm volatile("barrier.cluster.arrive.aligned;" ::: "memory");
    asm volatile("barrier.cluster.wait.aligned;"   ::: "memory");
}

// ---- packed f32x2 helpers (Blackwell FFMA2 — PTX-only) ----
typedef unsigned long long u64t;
static __device__ __forceinline__ u64t pack2ab(float a, float b) {
    u64t r; asm("mov.b64 %0, {%1, %2};" : "=l"(r) : "f"(a), "f"(b)); return r;
}
static __device__ __forceinline__ void unpack2(u64t p, float& a, float& b) {
    asm("mov.b64 {%0,%1}, %2;" : "=f"(a), "=f"(b) : "l"(p));
}
static __device__ __forceinline__ void ffma2(u64t& d, u64t a, u64t b) {
    asm("fma.rn.f32x2 %0, %1, %2, %0;" : "+l"(d) : "l"(a), "l"(b));
}
// one LDS.128 delivering two packed b64 vector pairs (no pack movs)
static __device__ __forceinline__ void lds_v2b64(uint32_t addr, u64t& lo, u64t& hi) {
    asm volatile("ld.shared.v2.b64 {%0, %1}, [%2];"
                 : "=l"(lo), "=l"(hi) : "r"(addr));
}
static __device__ __forceinline__ float rcp_fast(float x) {
    float r; asm("rcp.approx.f32 %0, %1;" : "=f"(r) : "f"(x)); return r;
}

struct alignas(16) ClusterSmem {
    float vec[2][C][S];              // double-buffered state vectors, per chunk
    unsigned long long full[2];      // mbarrier per buffer, count = CL*16 = 128
};

__global__ void __cluster_dims__(CL, 1, 1) __launch_bounds__(NT, 1)
hmm_scan(const float* __restrict__ obs, const float* __restrict__ A,
         const float* __restrict__ pi0)
{
    __shared__ ClusterSmem sm;

    const int tid = threadIdx.x;
    const int w = tid >> 5;
    const int l = tid & 31;
    const int ccg = (l >> 2) & 3;         // lane's chunk-within-group
    const int mcol = l & 3;               // lane's column within warp quad
    const int cluster = (int)blockIdx.x >> 3;
    const bool fwd = (cluster < NCLUS_DIR);
    const int dirIdx = fwd ? cluster : cluster - NCLUS_DIR;
    const uint32_t rank = my_rank();
    const int jbase = (int)rank * SLICE + 4 * w;
    const int jcol = jbase + mcol;
    float* gout = fwd ? g_alphas : g_betas;
    const int dir = fwd ? 1 : -1;

    // per-lane chunk params for its two chunks (group 0 and group 1)
    int base_g[2]; bool exact_g[2];
#pragma unroll
    for (int g = 0; g < 2; g++) {
        const int chunkid = dirIdx * C + g * 4 + ccg;
        const int store_lo = chunkid * LCHUNK;
        const bool ex = fwd ? (chunkid == 0) : (chunkid == NCHUNK - 1);
        exact_g[g] = ex;
        base_g[g] = ex ? (fwd ? 0 : NSTEP - 1)
                       : (fwd ? store_lo - BURN : store_lo + LCHUNK - 1 + BURN);
    }

    // ---- load A sub-block packed over k-row pairs ----
    // pA[(k*4+j)*2 + h]: h=0 holds rows (m=0,1), h=1 holds rows (m=2,3), col jbase+j
    u64t pA[32];
    if (fwd) {
#pragma unroll
        for (int k = 0; k < 4; k++) {
            const int r = 128 * k + 4 * l;
            float4 t0 = *reinterpret_cast<const float4*>(A + (size_t)(r + 0) * S + jbase);
            float4 t1 = *reinterpret_cast<const float4*>(A + (size_t)(r + 1) * S + jbase);
            float4 t2 = *reinterpret_cast<const float4*>(A + (size_t)(r + 2) * S + jbase);
            float4 t3 = *reinterpret_cast<const float4*>(A + (size_t)(r + 3) * S + jbase);
            pA[(k * 4 + 0) * 2 + 0] = pack2ab(t0.x, t1.x);
            pA[(k * 4 + 0) * 2 + 1] = pack2ab(t2.x, t3.x);
            pA[(k * 4 + 1) * 2 + 0] = pack2ab(t0.y, t1.y);
            pA[(k * 4 + 1) * 2 + 1] = pack2ab(t2.y, t3.y);
            pA[(k * 4 + 2) * 2 + 0] = pack2ab(t0.z, t1.z);
            pA[(k * 4 + 2) * 2 + 1] = pack2ab(t2.z, t3.z);
            pA[(k * 4 + 3) * 2 + 0] = pack2ab(t0.w, t1.w);
            pA[(k * 4 + 3) * 2 + 1] = pack2ab(t2.w, t3.w);
        }
    } else {
#pragma unroll
        for (int k = 0; k < 4; k++) {
            const int col0 = 128 * k + 4 * l;
#pragma unroll
            for (int j = 0; j < 4; j++) {
                float4 u = *reinterpret_cast<const float4*>(
                    A + (size_t)(jbase + j) * S + col0);
                pA[(k * 4 + j) * 2 + 0] = pack2ab(u.x, u.y);
                pA[(k * 4 + j) * 2 + 1] = pack2ab(u.z, u.w);
            }
        }
    }

    // ---- remote DSMEM addresses (group 0 buffer 0; +GRP_BYTES / +VBUF_BYTES) ----
    const int tr_base = (l >> 4) << 2;    // lanes 0-15 -> ranks 0-3, 16-31 -> 4-7
    uint32_t va[4];
#pragma unroll
    for (int r = 0; r < 4; r++)
        va[r] = mapa_u32(smem_u32(&sm.vec[0][ccg][jcol]), tr_base + r);
    const uint32_t fb    = mapa_u32(smem_u32(&sm.full[0]), l & 7);  // lanes 0-7
    const uint32_t full0 = smem_u32(&sm.full[0]);
    const uint32_t den0  = smem_u32(&sm.vec[0][ccg][0]);
    const uint32_t vbase = smem_u32(&sm.vec[0][0][0]) + (uint32_t)(l * 16);

    if (tid == 0) { mbar_init(full0, CL * 16); mbar_init(full0 + 8, CL * 16); }
    __syncthreads();
    cluster_sync_all();

    // ---- init step (s=0): buffer 0, both groups ----
    {
#pragma unroll
        for (int g = 0; g < 2; g++) {
            const int t0 = base_g[g];
            float ob0 = obs[(size_t)t0 * S + jcol];
            float val;
            if (fwd) {
                if (exact_g[g]) {
                    val = pi0[jcol] * ob0;
                    if (l < 16) gout[(size_t)t0 * S + jcol] = val;
                } else val = ob0;
            } else {
                val = ob0;
                if (exact_g[g] && l < 16) gout[(size_t)t0 * S + jcol] = 1.0f;
            }
            const uint32_t go = (uint32_t)(g * GRP_BYTES);
#pragma unroll
            for (int r = 0; r < 4; r++) st_cluster(va[r] + go, val);
        }
        __syncwarp();
        if (l < 8) mbar_arrive_remote(fb);
    }

    float ob_cur[2];
#pragma unroll
    for (int g = 0; g < 2; g++)
        ob_cur[g] = obs[(size_t)(base_g[g] + dir) * S + jcol];

    // ---- recurrence: 287 steps, 8 chunks each (2 groups of 4) ----
    for (int s = 1; s <= NSTEPS_LOOP; ++s) {
        const int p = (s - 1) & 1;
        const uint32_t ph = (uint32_t)((s - 1) >> 1) & 1u;
        const uint32_t pb = p ? (uint32_t)VBUF_BYTES : 0u;
        const uint32_t sb = (s & 1) ? (uint32_t)VBUF_BYTES : 0u;

        float ob_nxt[2] = {ob_cur[0], ob_cur[1]};
        if (s + 1 <= NSTEPS_LOOP) {
#pragma unroll
            for (int g = 0; g < 2; g++)
                ob_nxt[g] = obs[(size_t)(base_g[g] + dir * (s + 1)) * S + jcol];
        }

        mbar_wait_cluster(full0 + (p ? 8u : 0u), ph);

#pragma unroll
        for (int g = 0; g < 2; g++) {
            // normalization scalar: element 0 of this lane's chunk vector
            float den;
            asm volatile("ld.shared.f32 %0, [%1];" : "=f"(den)
                         : "r"(den0 + pb + (uint32_t)(g * GRP_BYTES)));
            const float inv = rcp_fast(den);

            // matvec for group's 4 chunks -> v[16]  (vi = cc*4 + j)
            float v[16];
#pragma unroll
            for (int cc = 0; cc < 4; cc++) {
                u64t a0 = 0ull, a1 = 0ull, a2 = 0ull, a3 = 0ull;
                const uint32_t ad = vbase + pb
                                  + (uint32_t)((g * 4 + cc) * CHUNK_BYTES);
#pragma unroll
                for (int k = 0; k < 4; k++) {
                    u64t vlo, vhi;
                    lds_v2b64(ad + (uint32_t)(k * 512), vlo, vhi);
                    ffma2(a0, vlo, pA[(k * 4 + 0) * 2 + 0]);
                    ffma2(a0, vhi, pA[(k * 4 + 0) * 2 + 1]);
                    ffma2(a1, vlo, pA[(k * 4 + 1) * 2 + 0]);
                    ffma2(a1, vhi, pA[(k * 4 + 1) * 2 + 1]);
                    ffma2(a2, vlo, pA[(k * 4 + 2) * 2 + 0]);
                    ffma2(a2, vhi, pA[(k * 4 + 2) * 2 + 1]);
                    ffma2(a3, vlo, pA[(k * 4 + 3) * 2 + 0]);
                    ffma2(a3, vhi, pA[(k * 4 + 3) * 2 + 1]);
                }
                float e, o;
                unpack2(a0, e, o); v[cc * 4 + 0] = e + o;
                unpack2(a1, e, o); v[cc * 4 + 1] = e + o;
                unpack2(a2, e, o); v[cc * 4 + 2] = e + o;
                unpack2(a3, e, o); v[cc * 4 + 3] = e + o;
            }

            // value-compaction reduction: lane l ends with total for vi = l&15
#pragma unroll
            for (int mm = 8; mm >= 1; mm >>= 1) {
                const bool up = (l & mm);
#pragma unroll
                for (int si = 0; si < mm; si++) {
                    float keep = up ? v[si + mm] : v[si];
                    float send = up ? v[si] : v[si + mm];
                    v[si] = keep + __shfl_xor_sync(~0u, send, mm);
                }
            }
            v[0] += __shfl_xor_sync(~0u, v[0], 16);

            const float dv  = v[0] * inv;
            const float val = dv * ob_cur[g];
            const int t_prod = base_g[g] + dir * s;
            const bool store_ok = exact_g[g] ? (s <= LCHUNK - 1) : (s >= BURN);
            if (l < 16 && store_ok)
                gout[(size_t)t_prod * S + jcol] = fwd ? val : dv;

            if (s < NSTEPS_LOOP) {
                const uint32_t go = sb + (uint32_t)(g * GRP_BYTES);
#pragma unroll
                for (int r = 0; r < 4; r++) st_cluster(va[r] + go, val);
            }
            ob_cur[g] = ob_nxt[g];
        }

        // per-warp arrive: warp-scope ordering, then lanes 0-7 hit all 8 ranks
        if (s < NSTEPS_LOOP) {
            __syncwarp();
            if (l < 8) mbar_arrive_remote(fb + ((s & 1) ? 8u : 0u));
        }
    }
    cluster_sync_all();   // keep smem alive until all remote traffic lands
}

// gamma_t = (alpha_t * beta_t) / rowsum — one warp per timestep
__global__ void __launch_bounds__(256) gamma_kernel(float* __restrict__ out)
{
    const int row = (int)((blockIdx.x * 256 + threadIdx.x) >> 5);
    const int l = threadIdx.x & 31;
    const float4* a4 = reinterpret_cast<const float4*>(g_alphas + (size_t)row * S);
    const float4* b4 = reinterpret_cast<const float4*>(g_betas  + (size_t)row * S);
    float4 pr[4];
    float s = 0.f;
#pragma unroll
    for (int k = 0; k < 4; k++) {
        float4 a = a4[k * 32 + l];
        float4 b = b4[k * 32 + l];
        float4 qv = make_float4(a.x * b.x, a.y * b.y, a.z * b.z, a.w * b.w);
        pr[k] = qv;
        s += (qv.x + qv.y) + (qv.z + qv.w);
    }
#pragma unroll
    for (int o = 16; o >= 1; o >>= 1) s += __shfl_xor_sync(~0u, s, o);
    const float inv = 1.0f / s;
    float4* o4 = reinterpret_cast<float4*>(out + (size_t)row * S);
#pragma unroll
    for (int k = 0; k < 4; k++) {
        float4 qv = pr[k];
        o4[k * 32 + l] = make_float4(qv.x * inv, qv.y * inv, qv.z * inv, qv.w * inv);
    }
}

extern "C" void kernel_launch(void* const* d_in, const int* in_sizes, int n_in,
                              void* d_out, int out_size)
{
    const float* obs = (const float*)d_in[0];   // [NSTEP, S]
    const float* A   = (const float*)d_in[1];   // [S, S]
    const float* pi0 = (const float*)d_in[2];   // [S]
    (void)in_sizes; (void)n_in; (void)out_size;

    hmm_scan<<<2 * NCLUS_DIR * CL, NT>>>(obs, A, pi0);
    gamma_kernel<<<(NSTEP * 32) / 256, 256>>>((float*)d_out);
}